// round 2
// baseline (speedup 1.0000x reference)
#include <cuda_runtime.h>
#include <math.h>

// ---------------------------------------------------------------------------
// Problem constants
// ---------------------------------------------------------------------------
#define BATCH  32
#define HH     56
#define WW_DIM 56
#define CC     384
#define HEADS  12
#define DH     32
#define WIN    7
#define SHIFT  3
#define NTOK   49              // tokens per window
#define NWIN   64              // windows per image (8x8)
#define HID    1536
#define TOK    (BATCH*HH*WW_DIM)       // 100352 tokens total
#define SCALE  0.17677669529663689f    // 32^-0.5

// ---------------------------------------------------------------------------
// Scratch (device globals; allocation in kernel_launch is forbidden)
// ---------------------------------------------------------------------------
__device__ __align__(16) float g_xw  [(size_t)TOK * CC];    // LN1'd, windowed tokens
__device__ __align__(16) float g_qkv [(size_t)TOK * 3*CC];  // qkv projections
__device__ __align__(16) float g_att [(size_t)TOK * CC];    // attention output (windowed order)
__device__ __align__(16) float g_y   [(size_t)TOK * CC];    // x + attn branch, [B,H,W,C] layout
__device__ __align__(16) float g_m   [(size_t)TOK * CC];    // LN2 output
__device__ __align__(16) float g_h   [(size_t)TOK * HID];   // MLP hidden

// ---------------------------------------------------------------------------
// Block reduction helper (128 threads)
// ---------------------------------------------------------------------------
__device__ __forceinline__ float block_sum128(float v) {
    __shared__ float sh[4];
    #pragma unroll
    for (int o = 16; o > 0; o >>= 1) v += __shfl_xor_sync(0xffffffffu, v, o);
    if ((threadIdx.x & 31) == 0) sh[threadIdx.x >> 5] = v;
    __syncthreads();
    float r = sh[0] + sh[1] + sh[2] + sh[3];
    __syncthreads();
    return r;
}

// ---------------------------------------------------------------------------
// LayerNorm (+ optional shift & window partition gather)
// grid = TOK, block = 128; each thread owns channels {tid, tid+128, tid+256}
// ---------------------------------------------------------------------------
template<bool WINDOWED>
__global__ void ln_kernel(const float* __restrict__ x,
                          const float* __restrict__ w,
                          const float* __restrict__ b,
                          float* __restrict__ out) {
    const int t = blockIdx.x;
    int src;
    if (WINDOWED) {
        const int win = t / NTOK, n = t % NTOK;
        const int bb = win >> 6, wh = (win >> 3) & 7, ww = win & 7;
        const int i = n / WIN, j = n % WIN;
        int h = wh * WIN + i + SHIFT;  if (h >= HH) h -= HH;       // roll(-SHIFT)
        int wc = ww * WIN + j + SHIFT; if (wc >= WW_DIM) wc -= WW_DIM;
        src = (bb * HH + h) * WW_DIM + wc;
    } else {
        src = t;
    }
    const float* xin = x + (size_t)src * CC;
    const int tid = threadIdx.x;
    const float v0 = xin[tid], v1 = xin[tid + 128], v2 = xin[tid + 256];

    const float mean = block_sum128(v0 + v1 + v2) * (1.0f / CC);
    const float d0 = v0 - mean, d1 = v1 - mean, d2 = v2 - mean;
    const float var = block_sum128(d0*d0 + d1*d1 + d2*d2) * (1.0f / CC);
    const float rstd = rsqrtf(var + 1e-5f);

    float* o = out + (size_t)t * CC;
    o[tid]       = d0 * rstd * w[tid]       + b[tid];
    o[tid + 128] = d1 * rstd * w[tid + 128] + b[tid + 128];
    o[tid + 256] = d2 * rstd * w[tid + 256] + b[tid + 256];
}

// ---------------------------------------------------------------------------
// SGEMM: Out[M,N] = A[M,K] @ Bm[K,N] (+ bias / epilogue)
// BM=BN=128, BK=8, 256 threads, 8x8 microtile. All dims divide tiles exactly.
// MODE 0: + bias                            (qkv)
// MODE 1: + bias, window-reverse+unshift scatter, + resid(x)   (proj)
// MODE 2: + bias, exact GELU                (fc1)
// MODE 3: + bias, + resid(y)                (fc2 -> d_out)
// ---------------------------------------------------------------------------
template<int MODE>
__global__ void __launch_bounds__(256, 2)
sgemm_kernel(const float* __restrict__ A, const float* __restrict__ Bm,
             const float* __restrict__ bias, const float* __restrict__ resid,
             float* __restrict__ Out, int M, int Nn, int K) {
    __shared__ float As[8][128];
    __shared__ float Bs[8][128];

    const int tid  = threadIdx.x;
    const int row0 = blockIdx.y * 128;
    const int col0 = blockIdx.x * 128;

    const int a_row = tid >> 1;          // 0..127
    const int a_col = (tid & 1) * 4;     // 0 or 4
    const int b_row = tid >> 5;          // 0..7
    const int b_col = (tid & 31) * 4;    // 0..124

    const int ty = tid >> 4, tx = tid & 15;

    float acc[8][8];
    #pragma unroll
    for (int i = 0; i < 8; i++)
        #pragma unroll
        for (int j = 0; j < 8; j++) acc[i][j] = 0.0f;

    for (int k0 = 0; k0 < K; k0 += 8) {
        const float4 av = *reinterpret_cast<const float4*>(
            &A[(size_t)(row0 + a_row) * K + k0 + a_col]);
        As[a_col + 0][a_row] = av.x;
        As[a_col + 1][a_row] = av.y;
        As[a_col + 2][a_row] = av.z;
        As[a_col + 3][a_row] = av.w;
        const float4 bv = *reinterpret_cast<const float4*>(
            &Bm[(size_t)(k0 + b_row) * Nn + col0 + b_col]);
        *reinterpret_cast<float4*>(&Bs[b_row][b_col]) = bv;
        __syncthreads();

        #pragma unroll
        for (int k = 0; k < 8; ++k) {
            float ra[8], rb[8];
            #pragma unroll
            for (int i = 0; i < 8; i++) ra[i] = As[k][ty * 8 + i];
            #pragma unroll
            for (int j = 0; j < 8; j++) rb[j] = Bs[k][tx * 8 + j];
            #pragma unroll
            for (int i = 0; i < 8; i++)
                #pragma unroll
                for (int j = 0; j < 8; j++) acc[i][j] += ra[i] * rb[j];
        }
        __syncthreads();
    }

    const int c0 = col0 + tx * 8;
    #pragma unroll
    for (int i = 0; i < 8; i++) {
        const int r = row0 + ty * 8 + i;
        size_t obase;
        if (MODE == 1) {
            // windowed token r -> [B,H,W,C] pixel after window-reverse + roll(+SHIFT)
            const int win = r / NTOK, n = r % NTOK;
            const int bb = win >> 6, wh = (win >> 3) & 7, ww = win & 7;
            const int ii = n / WIN, jj = n % WIN;
            int h = wh * WIN + ii + SHIFT;  if (h >= HH) h -= HH;
            int wc = ww * WIN + jj + SHIFT; if (wc >= WW_DIM) wc -= WW_DIM;
            obase = ((size_t)(bb * HH + h) * WW_DIM + wc) * CC;
        } else {
            obase = (size_t)r * Nn;
        }
        #pragma unroll
        for (int j4 = 0; j4 < 8; j4 += 4) {
            float4 v;
            v.x = acc[i][j4 + 0] + bias[c0 + j4 + 0];
            v.y = acc[i][j4 + 1] + bias[c0 + j4 + 1];
            v.z = acc[i][j4 + 2] + bias[c0 + j4 + 2];
            v.w = acc[i][j4 + 3] + bias[c0 + j4 + 3];
            if (MODE == 2) {
                v.x = 0.5f * v.x * (1.0f + erff(v.x * 0.70710678118654752f));
                v.y = 0.5f * v.y * (1.0f + erff(v.y * 0.70710678118654752f));
                v.z = 0.5f * v.z * (1.0f + erff(v.z * 0.70710678118654752f));
                v.w = 0.5f * v.w * (1.0f + erff(v.w * 0.70710678118654752f));
            }
            if (MODE == 1 || MODE == 3) {
                const float4 rr = *reinterpret_cast<const float4*>(&resid[obase + c0 + j4]);
                v.x += rr.x; v.y += rr.y; v.z += rr.z; v.w += rr.w;
            }
            *reinterpret_cast<float4*>(&Out[obase + c0 + j4]) = v;
        }
    }
}

// ---------------------------------------------------------------------------
// Fused windowed attention: one block per (window, head).
// scores + rel-pos bias + shift mask + softmax + A@V entirely in SMEM.
// ---------------------------------------------------------------------------
__global__ void __launch_bounds__(128)
attn_kernel(const float* __restrict__ qkv, const float* __restrict__ rpb,
            float* __restrict__ out) {
    __shared__ float qs[NTOK][DH];
    __shared__ float ks[NTOK][DH];
    __shared__ float vs[NTOK][DH];
    __shared__ float S[NTOK][52];

    const int blk  = blockIdx.x;
    const int head = blk % HEADS;
    const int win  = blk / HEADS;
    const int tid  = threadIdx.x;

    const size_t base = (size_t)win * NTOK * (3 * CC) + head * DH;
    for (int p = tid; p < NTOK * DH; p += 128) {
        const int n = p >> 5, d = p & 31;
        const size_t r = base + (size_t)n * (3 * CC) + d;
        qs[n][d] = qkv[r] * SCALE;
        ks[n][d] = qkv[r + CC];
        vs[n][d] = qkv[r + 2 * CC];
    }
    __syncthreads();

    const int wh = (win >> 3) & 7, ww = win & 7;
    for (int p = tid; p < NTOK * NTOK; p += 128) {
        const int n = p / NTOK, m = p % NTOK;
        float s = 0.0f;
        #pragma unroll
        for (int d = 0; d < DH; d++) s += qs[n][d] * ks[m][d];
        const int in_ = n / WIN, jn = n % WIN, im = m / WIN, jm = m % WIN;
        // relative position bias
        const int rel = (in_ - im + WIN - 1) * (2 * WIN - 1) + (jn - jm + WIN - 1);
        s += rpb[rel * HEADS + head];
        // shifted-window mask: region of each pixel in the shifted image
        const int hn = wh * WIN + in_, hm = wh * WIN + im;
        const int wn = ww * WIN + jn,  wm = ww * WIN + jm;
        const int rn = (hn < HH-WIN ? 0 : (hn < HH-SHIFT ? 1 : 2)) * 3
                     + (wn < WW_DIM-WIN ? 0 : (wn < WW_DIM-SHIFT ? 1 : 2));
        const int rm = (hm < HH-WIN ? 0 : (hm < HH-SHIFT ? 1 : 2)) * 3
                     + (wm < WW_DIM-WIN ? 0 : (wm < WW_DIM-SHIFT ? 1 : 2));
        if (rn != rm) s -= 100.0f;
        S[n][m] = s;
    }
    __syncthreads();

    if (tid < NTOK) {
        float mx = -1e30f;
        #pragma unroll 7
        for (int m = 0; m < NTOK; m++) mx = fmaxf(mx, S[tid][m]);
        float sum = 0.0f;
        #pragma unroll 7
        for (int m = 0; m < NTOK; m++) {
            const float e = __expf(S[tid][m] - mx);
            S[tid][m] = e;
            sum += e;
        }
        const float inv = 1.0f / sum;
        #pragma unroll 7
        for (int m = 0; m < NTOK; m++) S[tid][m] *= inv;
    }
    __syncthreads();

    for (int p = tid; p < NTOK * DH; p += 128) {
        const int n = p >> 5, d = p & 31;
        float s = 0.0f;
        #pragma unroll 7
        for (int m = 0; m < NTOK; m++) s += S[n][m] * vs[m][d];
        out[(size_t)(win * NTOK + n) * CC + head * DH + d] = s;
    }
}

// ---------------------------------------------------------------------------
// Launch
// ---------------------------------------------------------------------------
extern "C" void kernel_launch(void* const* d_in, const int* in_sizes, int n_in,
                              void* d_out, int out_size) {
    const float* x       = (const float*)d_in[0];
    const float* norm1_w = (const float*)d_in[1];
    const float* norm1_b = (const float*)d_in[2];
    const float* qkv_w   = (const float*)d_in[3];
    const float* qkv_b   = (const float*)d_in[4];
    const float* proj_w  = (const float*)d_in[5];
    const float* proj_b  = (const float*)d_in[6];
    const float* rpb     = (const float*)d_in[7];
    const float* norm2_w = (const float*)d_in[8];
    const float* norm2_b = (const float*)d_in[9];
    const float* fc1_w   = (const float*)d_in[10];
    const float* fc1_b   = (const float*)d_in[11];
    const float* fc2_w   = (const float*)d_in[12];
    const float* fc2_b   = (const float*)d_in[13];
    float* out = (float*)d_out;

    float *xw, *qkv, *att, *y, *m, *h;
    cudaGetSymbolAddress((void**)&xw,  g_xw);
    cudaGetSymbolAddress((void**)&qkv, g_qkv);
    cudaGetSymbolAddress((void**)&att, g_att);
    cudaGetSymbolAddress((void**)&y,   g_y);
    cudaGetSymbolAddress((void**)&m,   g_m);
    cudaGetSymbolAddress((void**)&h,   g_h);

    // 1. LN1 + shift + window partition
    ln_kernel<true><<<TOK, 128>>>(x, norm1_w, norm1_b, xw);
    // 2. qkv GEMM: [100352,384] @ [384,1152]
    sgemm_kernel<0><<<dim3((3*CC)/128, TOK/128), 256>>>(xw, qkv_w, qkv_b, nullptr,
                                                        qkv, TOK, 3*CC, CC);
    // 3. fused windowed attention
    attn_kernel<<<BATCH * NWIN * HEADS, 128>>>(qkv, rpb, att);
    // 4. proj GEMM + window-reverse + unshift + residual
    sgemm_kernel<1><<<dim3(CC/128, TOK/128), 256>>>(att, proj_w, proj_b, x,
                                                    y, TOK, CC, CC);
    // 5. LN2
    ln_kernel<false><<<TOK, 128>>>(y, norm2_w, norm2_b, m);
    // 6. fc1 + GELU
    sgemm_kernel<2><<<dim3(HID/128, TOK/128), 256>>>(m, fc1_w, fc1_b, nullptr,
                                                     h, TOK, HID, CC);
    // 7. fc2 + residual -> d_out
    sgemm_kernel<3><<<dim3(CC/128, TOK/128), 256>>>(h, fc2_w, fc2_b, y,
                                                    out, TOK, CC, HID);
}

// round 11
// speedup vs baseline: 4.7254x; 4.7254x over previous
#include <cuda_runtime.h>
#include <cuda_bf16.h>
#include <math.h>
#include <stdint.h>

// ---------------------------------------------------------------------------
// Problem constants
// ---------------------------------------------------------------------------
#define BATCH  32
#define HH     56
#define WW_DIM 56
#define CC     384
#define HEADS  12
#define DH     32
#define WIN    7
#define SHIFT  3
#define NTOK   49
#define NWIN   64
#define HID    1536
#define TOK    (BATCH*HH*WW_DIM)       // 100352
#define SCALE  0.17677669529663689f

// ---------------------------------------------------------------------------
// Scratch (device globals)
// ---------------------------------------------------------------------------
__device__ __align__(16) __nv_bfloat16 g_xw [(size_t)TOK * CC];
__device__ __align__(16) __nv_bfloat16 g_qkv[(size_t)TOK * 3*CC];
__device__ __align__(16) __nv_bfloat16 g_att[(size_t)TOK * CC];
__device__ __align__(16) float         g_y  [(size_t)TOK * CC];
__device__ __align__(16) __nv_bfloat16 g_m  [(size_t)TOK * CC];
__device__ __align__(16) __nv_bfloat16 g_h  [(size_t)TOK * HID];
// transposed bf16 weights, [N,K] K-contiguous (== col-major B for mma .row.col)
__device__ __align__(16) __nv_bfloat16 g_wqkv[(size_t)(3*CC) * CC];
__device__ __align__(16) __nv_bfloat16 g_wproj[(size_t)CC * CC];
__device__ __align__(16) __nv_bfloat16 g_wfc1[(size_t)HID * CC];
__device__ __align__(16) __nv_bfloat16 g_wfc2[(size_t)CC * HID];

// ---------------------------------------------------------------------------
// HMMA / cp.async helpers (Ampere-era PTX; valid on plain sm_103 target)
// ---------------------------------------------------------------------------
__device__ __forceinline__ uint32_t smem_u32(const void* p) {
    uint32_t a;
    asm("{ .reg .u64 t; cvta.to.shared.u64 t, %1; cvt.u32.u64 %0, t; }" : "=r"(a) : "l"(p));
    return a;
}
#define LDSM_X4(r0, r1, r2, r3, addr)                                          \
    asm volatile("ldmatrix.sync.aligned.m8n8.x4.shared.b16 {%0,%1,%2,%3}, [%4];" \
        : "=r"(r0), "=r"(r1), "=r"(r2), "=r"(r3) : "r"(addr))

#define MMA16816(d, a, b)                                                      \
    asm volatile("mma.sync.aligned.m16n8k16.row.col.f32.bf16.bf16.f32 "        \
        "{%0,%1,%2,%3}, {%4,%5,%6,%7}, {%8,%9}, {%0,%1,%2,%3};"                \
        : "+f"((d)[0]), "+f"((d)[1]), "+f"((d)[2]), "+f"((d)[3])               \
        : "r"((a)[0]), "r"((a)[1]), "r"((a)[2]), "r"((a)[3]),                  \
          "r"((b)[0]), "r"((b)[1]))

#define CP_ASYNC16(dst, src)                                                   \
    asm volatile("cp.async.cg.shared.global [%0], [%1], 16;" :: "r"(dst), "l"(src))
#define CP_COMMIT()  asm volatile("cp.async.commit_group;" ::: "memory")
#define CP_WAIT0()   asm volatile("cp.async.wait_group 0;" ::: "memory")
#define CP_WAIT1()   asm volatile("cp.async.wait_group 1;" ::: "memory")

// ---------------------------------------------------------------------------
// Weight transpose + bf16: wt[n*K+k] = bf16(w[k*N+n])
// ---------------------------------------------------------------------------
__global__ void wtrans_kernel(const float* __restrict__ w, __nv_bfloat16* __restrict__ wt,
                              int K, int N) {
    int idx = blockIdx.x * 256 + threadIdx.x;
    if (idx >= K * N) return;
    int n = idx / K, k = idx % K;
    wt[idx] = __float2bfloat16(w[(size_t)k * N + n]);
}

// ---------------------------------------------------------------------------
// Block reduction (128 threads)
// ---------------------------------------------------------------------------
__device__ __forceinline__ float block_sum128(float v) {
    __shared__ float sh[4];
    #pragma unroll
    for (int o = 16; o > 0; o >>= 1) v += __shfl_xor_sync(0xffffffffu, v, o);
    if ((threadIdx.x & 31) == 0) sh[threadIdx.x >> 5] = v;
    __syncthreads();
    float r = sh[0] + sh[1] + sh[2] + sh[3];
    __syncthreads();
    return r;
}

// ---------------------------------------------------------------------------
// LayerNorm -> bf16 (optionally shift + window-partition gather)
// ---------------------------------------------------------------------------
template<bool WINDOWED>
__global__ void ln_kernel(const float* __restrict__ x, const float* __restrict__ w,
                          const float* __restrict__ b, __nv_bfloat16* __restrict__ out) {
    const int t = blockIdx.x;
    int src;
    if (WINDOWED) {
        const int win = t / NTOK, n = t % NTOK;
        const int bb = win >> 6, wh = (win >> 3) & 7, ww = win & 7;
        const int i = n / WIN, j = n % WIN;
        int h = wh * WIN + i + SHIFT;  if (h >= HH) h -= HH;
        int wc = ww * WIN + j + SHIFT; if (wc >= WW_DIM) wc -= WW_DIM;
        src = (bb * HH + h) * WW_DIM + wc;
    } else {
        src = t;
    }
    const float* xin = x + (size_t)src * CC;
    const int tid = threadIdx.x;
    const float v0 = xin[tid], v1 = xin[tid + 128], v2 = xin[tid + 256];
    const float mean = block_sum128(v0 + v1 + v2) * (1.0f / CC);
    const float d0 = v0 - mean, d1 = v1 - mean, d2 = v2 - mean;
    const float var = block_sum128(d0*d0 + d1*d1 + d2*d2) * (1.0f / CC);
    const float rstd = rsqrtf(var + 1e-5f);
    __nv_bfloat16* o = out + (size_t)t * CC;
    o[tid]       = __float2bfloat16(d0 * rstd * w[tid]       + b[tid]);
    o[tid + 128] = __float2bfloat16(d1 * rstd * w[tid + 128] + b[tid + 128]);
    o[tid + 256] = __float2bfloat16(d2 * rstd * w[tid + 256] + b[tid + 256]);
}

// ---------------------------------------------------------------------------
// HMMA bf16 GEMM: Out[M,N] = A[M,K] @ Bt[N,K]^T
// BM=BN=128, BK=32, 256 threads (8 warps, 4x2), warp tile 32x64.
// cp.async double-buffered mainloop.
// MODE 0: +bias -> bf16                     (qkv)
// MODE 1: +bias, scatter+resid(x) -> f32    (proj)
// MODE 2: +bias, GELU -> bf16               (fc1)
// MODE 3: +bias, +resid(y) -> f32           (fc2)
// ---------------------------------------------------------------------------
template<int MODE>
__global__ void __launch_bounds__(256, 2)
hmma_gemm(const __nv_bfloat16* __restrict__ A, const __nv_bfloat16* __restrict__ Bt,
          const float* __restrict__ bias, const float* __restrict__ resid,
          void* __restrict__ OutV, int Nn, int K) {
    __shared__ __nv_bfloat16 sA[2][128][40];   // pad: 80B row stride, LDSM conflict-free
    __shared__ __nv_bfloat16 sB[2][128][40];

    const int tid  = threadIdx.x;
    const int lane = tid & 31, warp = tid >> 5;
    const int m0 = (warp & 3) * 32;       // warp M offset in tile
    const int n0 = (warp >> 2) * 64;      // warp N offset in tile
    const int row0 = blockIdx.y * 128;
    const int col0 = blockIdx.x * 128;

    // per-thread load slots (2 x uint4 per array per chunk)
    const int ld_r0 = tid >> 2,           ld_c0 = (tid & 3) * 8;
    const int ld_r1 = (tid + 256) >> 2,   ld_c1 = ld_c0;

    float acc[2][8][4];
    #pragma unroll
    for (int mt = 0; mt < 2; mt++)
        #pragma unroll
        for (int nt = 0; nt < 8; nt++)
            #pragma unroll
            for (int i = 0; i < 4; i++) acc[mt][nt][i] = 0.0f;

    // ldmatrix address components
    const int a_r = lane & 15, a_c8 = (lane >> 4) * 8;
    const int b_g = lane >> 3, b_r = lane & 7;
    const int b_row_off = ((b_g >> 1) << 3) + b_r;   // 0..15
    const int b_c8 = (b_g & 1) * 8;

    const int nch = K >> 5;

    // prologue: chunk 0 -> buffer 0
    {
        CP_ASYNC16(smem_u32(&sA[0][ld_r0][ld_c0]), &A[(size_t)(row0 + ld_r0) * K + ld_c0]);
        CP_ASYNC16(smem_u32(&sB[0][ld_r0][ld_c0]), &Bt[(size_t)(col0 + ld_r0) * K + ld_c0]);
        CP_ASYNC16(smem_u32(&sA[0][ld_r1][ld_c1]), &A[(size_t)(row0 + ld_r1) * K + ld_c1]);
        CP_ASYNC16(smem_u32(&sB[0][ld_r1][ld_c1]), &Bt[(size_t)(col0 + ld_r1) * K + ld_c1]);
        CP_COMMIT();
    }

    for (int kc = 0; kc < nch; kc++) {
        const int buf = kc & 1;
        if (kc + 1 < nch) {
            const int nb = (kc + 1) & 1;
            const int ko = (kc + 1) * 32;
            CP_ASYNC16(smem_u32(&sA[nb][ld_r0][ld_c0]), &A[(size_t)(row0 + ld_r0) * K + ko + ld_c0]);
            CP_ASYNC16(smem_u32(&sB[nb][ld_r0][ld_c0]), &Bt[(size_t)(col0 + ld_r0) * K + ko + ld_c0]);
            CP_ASYNC16(smem_u32(&sA[nb][ld_r1][ld_c1]), &A[(size_t)(row0 + ld_r1) * K + ko + ld_c1]);
            CP_ASYNC16(smem_u32(&sB[nb][ld_r1][ld_c1]), &Bt[(size_t)(col0 + ld_r1) * K + ko + ld_c1]);
            CP_COMMIT();
            CP_WAIT1();
        } else {
            CP_WAIT0();
        }
        __syncthreads();

        #pragma unroll
        for (int kk = 0; kk < 32; kk += 16) {
            uint32_t afr[2][4];
            #pragma unroll
            for (int mt = 0; mt < 2; mt++) {
                const uint32_t addr = smem_u32(&sA[buf][m0 + mt * 16 + a_r][kk + a_c8]);
                LDSM_X4(afr[mt][0], afr[mt][1], afr[mt][2], afr[mt][3], addr);
            }
            uint32_t bfr[8][2];
            #pragma unroll
            for (int nt2 = 0; nt2 < 4; nt2++) {
                const uint32_t addr = smem_u32(&sB[buf][n0 + nt2 * 16 + b_row_off][kk + b_c8]);
                LDSM_X4(bfr[nt2*2][0], bfr[nt2*2][1], bfr[nt2*2+1][0], bfr[nt2*2+1][1], addr);
            }
            #pragma unroll
            for (int mt = 0; mt < 2; mt++)
                #pragma unroll
                for (int nt = 0; nt < 8; nt++)
                    MMA16816(acc[mt][nt], afr[mt], bfr[nt]);
        }
        __syncthreads();
    }

    // epilogue: thread holds (r, c..c+1) and (r+8, c..c+1) per (mt, nt)
    #pragma unroll
    for (int mt = 0; mt < 2; mt++) {
        #pragma unroll
        for (int half = 0; half < 2; half++) {
            const int r = row0 + m0 + mt * 16 + (lane >> 2) + half * 8;
            size_t obase;
            if (MODE == 1) {
                const int win = r / NTOK, n = r % NTOK;
                const int bb = win >> 6, wh = (win >> 3) & 7, ww = win & 7;
                const int ii = n / WIN, jj = n % WIN;
                int h = wh * WIN + ii + SHIFT;  if (h >= HH) h -= HH;
                int wc = ww * WIN + jj + SHIFT; if (wc >= WW_DIM) wc -= WW_DIM;
                obase = ((size_t)(bb * HH + h) * WW_DIM + wc) * CC;
            } else {
                obase = (size_t)r * Nn;
            }
            #pragma unroll
            for (int nt = 0; nt < 8; nt++) {
                const int c = col0 + n0 + nt * 8 + (lane & 3) * 2;
                float v0 = acc[mt][nt][half * 2 + 0] + bias[c];
                float v1 = acc[mt][nt][half * 2 + 1] + bias[c + 1];
                if (MODE == 2) {
                    v0 = 0.5f * v0 * (1.0f + erff(v0 * 0.70710678118654752f));
                    v1 = 0.5f * v1 * (1.0f + erff(v1 * 0.70710678118654752f));
                }
                if (MODE == 0 || MODE == 2) {
                    __nv_bfloat16* Out = (__nv_bfloat16*)OutV;
                    *reinterpret_cast<__nv_bfloat162*>(Out + obase + c) =
                        __floats2bfloat162_rn(v0, v1);
                } else {
                    float* Out = (float*)OutV;
                    const float2 rr2 = *reinterpret_cast<const float2*>(&resid[obase + c]);
                    float2 o2 = make_float2(v0 + rr2.x, v1 + rr2.y);
                    *reinterpret_cast<float2*>(Out + obase + c) = o2;
                }
            }
        }
    }
}

// ---------------------------------------------------------------------------
// Windowed attention: block = (window, head-pair), 128 threads.
// K/V bf16 in smem (broadcast reads), scores f32 in smem (stride 53), q in regs.
// ---------------------------------------------------------------------------
__global__ void __launch_bounds__(128)
attn_kernel(const __nv_bfloat16* __restrict__ qkv, const float* __restrict__ rpb,
            __nv_bfloat16* __restrict__ out) {
    __shared__ __nv_bfloat16 ks[2][NTOK][DH];
    __shared__ __nv_bfloat16 vs[2][NTOK][DH];
    __shared__ float S[2][NTOK][53];

    const int win = blockIdx.x;
    const int hp  = blockIdx.y;          // head pair 0..5
    const int tid = threadIdx.x;
    const int hh  = tid >> 6;            // 0/1
    const int n   = tid & 63;
    const int head = hp * 2 + hh;

    // cooperative K/V load: 196 rows of 64B (k then v, both heads)
    const size_t wbase = (size_t)win * NTOK * (3 * CC);
    for (int idx = tid; idx < 196 * 4; idx += 128) {
        const int row = idx >> 2, c = idx & 3;
        const int kv = row / 98;               // 0=k, 1=v
        const int rr = row % 98;
        const int hx = rr / NTOK, nn = rr % NTOK;
        const uint4 u = *reinterpret_cast<const uint4*>(
            qkv + wbase + (size_t)nn * (3 * CC) + (kv + 1) * CC + (hp * 2 + hx) * DH + c * 8);
        __nv_bfloat16* dst = (kv == 0 ? &ks[hx][nn][0] : &vs[hx][nn][0]);
        *reinterpret_cast<uint4*>(dst + c * 8) = u;
    }
    __syncthreads();

    if (n < NTOK) {
        // q row into registers (scaled)
        float q[DH];
        {
            const __nv_bfloat16* qp = qkv + wbase + (size_t)n * (3 * CC) + head * DH;
            #pragma unroll
            for (int c = 0; c < 4; c++) {
                const uint4 u = *reinterpret_cast<const uint4*>(qp + c * 8);
                const uint32_t w4[4] = {u.x, u.y, u.z, u.w};
                #pragma unroll
                for (int j = 0; j < 4; j++) {
                    const float2 fv = __bfloat1622float2(
                        *reinterpret_cast<const __nv_bfloat162*>(&w4[j]));
                    q[c*8 + j*2]     = fv.x * SCALE;
                    q[c*8 + j*2 + 1] = fv.y * SCALE;
                }
            }
        }
        const int wh = (win >> 3) & 7, ww = win & 7;
        const int in_ = n / WIN, jn = n % WIN;
        const int hn = wh * WIN + in_, wn = ww * WIN + jn;
        const int rn = (hn < HH-WIN ? 0 : (hn < HH-SHIFT ? 1 : 2)) * 3
                     + (wn < WW_DIM-WIN ? 0 : (wn < WW_DIM-SHIFT ? 1 : 2));

        // scores
        for (int m = 0; m < NTOK; m++) {
            const int im = m / WIN, jm = m % WIN;
            const int hm = wh * WIN + im, wm = ww * WIN + jm;
            const int rm = (hm < HH-WIN ? 0 : (hm < HH-SHIFT ? 1 : 2)) * 3
                         + (wm < WW_DIM-WIN ? 0 : (wm < WW_DIM-SHIFT ? 1 : 2));
            const int rel = (in_ - im + WIN - 1) * (2*WIN - 1) + (jn - jm + WIN - 1);
            float s = rpb[rel * HEADS + head] + (rn != rm ? -100.0f : 0.0f);
            const __nv_bfloat162* kp = reinterpret_cast<const __nv_bfloat162*>(&ks[hh][m][0]);
            #pragma unroll
            for (int d2 = 0; d2 < 16; d2++) {
                const float2 kv2 = __bfloat1622float2(kp[d2]);
                s += q[2*d2] * kv2.x + q[2*d2+1] * kv2.y;
            }
            S[hh][n][m] = s;
        }
        // softmax over own row
        float mx = -1e30f;
        for (int m = 0; m < NTOK; m++) mx = fmaxf(mx, S[hh][n][m]);
        float sum = 0.0f;
        for (int m = 0; m < NTOK; m++) {
            const float e = __expf(S[hh][n][m] - mx);
            S[hh][n][m] = e;
            sum += e;
        }
        const float inv = 1.0f / sum;
        // A @ V
        float acc[DH];
        #pragma unroll
        for (int d = 0; d < DH; d++) acc[d] = 0.0f;
        for (int m = 0; m < NTOK; m++) {
            const float p = S[hh][n][m];
            const __nv_bfloat162* vp = reinterpret_cast<const __nv_bfloat162*>(&vs[hh][m][0]);
            #pragma unroll
            for (int d2 = 0; d2 < 16; d2++) {
                const float2 vv = __bfloat1622float2(vp[d2]);
                acc[2*d2]   += p * vv.x;
                acc[2*d2+1] += p * vv.y;
            }
        }
        // store
        __nv_bfloat16* op = out + (size_t)(win * NTOK + n) * CC + head * DH;
        #pragma unroll
        for (int c = 0; c < 4; c++) {
            uint4 u;
            uint32_t* uw = &u.x;
            #pragma unroll
            for (int j = 0; j < 4; j++) {
                const __nv_bfloat162 hv = __floats2bfloat162_rn(acc[c*8 + j*2] * inv,
                                                                acc[c*8 + j*2 + 1] * inv);
                uw[j] = *reinterpret_cast<const uint32_t*>(&hv);
            }
            *reinterpret_cast<uint4*>(op + c * 8) = u;
        }
    }
}

// ---------------------------------------------------------------------------
// Launch
// ---------------------------------------------------------------------------
extern "C" void kernel_launch(void* const* d_in, const int* in_sizes, int n_in,
                              void* d_out, int out_size) {
    const float* x       = (const float*)d_in[0];
    const float* norm1_w = (const float*)d_in[1];
    const float* norm1_b = (const float*)d_in[2];
    const float* qkv_w   = (const float*)d_in[3];
    const float* qkv_b   = (const float*)d_in[4];
    const float* proj_w  = (const float*)d_in[5];
    const float* proj_b  = (const float*)d_in[6];
    const float* rpb     = (const float*)d_in[7];
    const float* norm2_w = (const float*)d_in[8];
    const float* norm2_b = (const float*)d_in[9];
    const float* fc1_w   = (const float*)d_in[10];
    const float* fc1_b   = (const float*)d_in[11];
    const float* fc2_w   = (const float*)d_in[12];
    const float* fc2_b   = (const float*)d_in[13];
    float* out = (float*)d_out;

    __nv_bfloat16 *xw, *qkv, *att, *m, *h, *wqkv, *wproj, *wfc1, *wfc2;
    float *y;
    cudaGetSymbolAddress((void**)&xw,   g_xw);
    cudaGetSymbolAddress((void**)&qkv,  g_qkv);
    cudaGetSymbolAddress((void**)&att,  g_att);
    cudaGetSymbolAddress((void**)&y,    g_y);
    cudaGetSymbolAddress((void**)&m,    g_m);
    cudaGetSymbolAddress((void**)&h,    g_h);
    cudaGetSymbolAddress((void**)&wqkv, g_wqkv);
    cudaGetSymbolAddress((void**)&wproj,g_wproj);
    cudaGetSymbolAddress((void**)&wfc1, g_wfc1);
    cudaGetSymbolAddress((void**)&wfc2, g_wfc2);

    // weight transposes (bf16, [N,K])
    wtrans_kernel<<<(CC*3*CC + 255)/256, 256>>>(qkv_w, wqkv, CC, 3*CC);
    wtrans_kernel<<<(CC*CC   + 255)/256, 256>>>(proj_w, wproj, CC, CC);
    wtrans_kernel<<<(CC*HID  + 255)/256, 256>>>(fc1_w, wfc1, CC, HID);
    wtrans_kernel<<<(HID*CC  + 255)/256, 256>>>(fc2_w, wfc2, HID, CC);

    // 1. LN1 + shift + window partition -> bf16
    ln_kernel<true><<<TOK, 128>>>(x, norm1_w, norm1_b, xw);
    // 2. qkv GEMM
    hmma_gemm<0><<<dim3((3*CC)/128, TOK/128), 256>>>(xw, wqkv, qkv_b, nullptr, qkv, 3*CC, CC);
    // 3. attention
    attn_kernel<<<dim3(BATCH*NWIN, HEADS/2), 128>>>(qkv, rpb, att);
    // 4. proj GEMM + window-reverse + unshift + residual -> y (f32)
    hmma_gemm<1><<<dim3(CC/128, TOK/128), 256>>>(att, wproj, proj_b, x, y, CC, CC);
    // 5. LN2 -> bf16
    ln_kernel<false><<<TOK, 128>>>(y, norm2_w, norm2_b, m);
    // 6. fc1 + GELU -> bf16
    hmma_gemm<2><<<dim3(HID/128, TOK/128), 256>>>(m, wfc1, fc1_b, nullptr, h, HID, CC);
    // 7. fc2 + residual -> d_out (f32)
    hmma_gemm<3><<<dim3(CC/128, TOK/128), 256>>>(h, wfc2, fc2_b, y, out, CC, HID);
}

// round 14
// speedup vs baseline: 4.7469x; 1.0046x over previous
#include <cuda_runtime.h>
#include <cuda_bf16.h>
#include <math.h>
#include <stdint.h>

// ---------------------------------------------------------------------------
// Problem constants
// ---------------------------------------------------------------------------
#define BATCH  32
#define HH     56
#define WW_DIM 56
#define CC     384
#define HEADS  12
#define DH     32
#define WIN    7
#define SHIFT  3
#define NTOK   49
#define NWIN   64
#define HID    1536
#define TOK    (BATCH*HH*WW_DIM)       // 100352
#define SCALE  0.17677669529663689f

// ---------------------------------------------------------------------------
// Scratch (device globals)
// ---------------------------------------------------------------------------
__device__ __align__(16) __nv_bfloat16 g_xw [(size_t)TOK * CC];
__device__ __align__(16) __nv_bfloat16 g_qkv[(size_t)TOK * 3*CC];
__device__ __align__(16) __nv_bfloat16 g_att[(size_t)TOK * CC];
__device__ __align__(16) float         g_y  [(size_t)TOK * CC];
__device__ __align__(16) __nv_bfloat16 g_m  [(size_t)TOK * CC];
__device__ __align__(16) __nv_bfloat16 g_h  [(size_t)TOK * HID];
// transposed bf16 weights, [N,K] K-contiguous (== col-major B for mma .row.col)
__device__ __align__(16) __nv_bfloat16 g_wqkv[(size_t)(3*CC) * CC];
__device__ __align__(16) __nv_bfloat16 g_wproj[(size_t)CC * CC];
__device__ __align__(16) __nv_bfloat16 g_wfc1[(size_t)HID * CC];
__device__ __align__(16) __nv_bfloat16 g_wfc2[(size_t)CC * HID];

// ---------------------------------------------------------------------------
// HMMA / cp.async helpers (Ampere-era PTX; valid on plain sm_103 target)
// ---------------------------------------------------------------------------
__device__ __forceinline__ uint32_t smem_u32(const void* p) {
    uint32_t a;
    asm("{ .reg .u64 t; cvta.to.shared.u64 t, %1; cvt.u32.u64 %0, t; }" : "=r"(a) : "l"(p));
    return a;
}
#define LDSM_X4(r0, r1, r2, r3, addr)                                          \
    asm volatile("ldmatrix.sync.aligned.m8n8.x4.shared.b16 {%0,%1,%2,%3}, [%4];" \
        : "=r"(r0), "=r"(r1), "=r"(r2), "=r"(r3) : "r"(addr))

#define MMA16816(d, a, b)                                                      \
    asm volatile("mma.sync.aligned.m16n8k16.row.col.f32.bf16.bf16.f32 "        \
        "{%0,%1,%2,%3}, {%4,%5,%6,%7}, {%8,%9}, {%0,%1,%2,%3};"                \
        : "+f"((d)[0]), "+f"((d)[1]), "+f"((d)[2]), "+f"((d)[3])               \
        : "r"((a)[0]), "r"((a)[1]), "r"((a)[2]), "r"((a)[3]),                  \
          "r"((b)[0]), "r"((b)[1]))

#define CP_ASYNC16(dst, src)                                                   \
    asm volatile("cp.async.cg.shared.global [%0], [%1], 16;" :: "r"(dst), "l"(src))
#define CP_COMMIT()  asm volatile("cp.async.commit_group;" ::: "memory")
#define CP_WAIT0()   asm volatile("cp.async.wait_group 0;" ::: "memory")
#define CP_WAIT1()   asm volatile("cp.async.wait_group 1;" ::: "memory")

// ---------------------------------------------------------------------------
// Merged weight transpose + bf16 for all four matrices in ONE launch.
// wt[n*K+k] = bf16(w[k*N+n]) per segment.
// ---------------------------------------------------------------------------
#define S_QKV  (3*CC*CC)      // 442368
#define S_PROJ (CC*CC)        // 147456
#define S_FC1  (CC*HID)       // 589824
#define S_FC2  (HID*CC)       // 589824
#define S_TOT  (S_QKV + S_PROJ + S_FC1 + S_FC2)   // 1769472

__global__ void wtrans_all(const float* __restrict__ qkv_w, const float* __restrict__ proj_w,
                           const float* __restrict__ fc1_w, const float* __restrict__ fc2_w,
                           __nv_bfloat16* __restrict__ wqkv, __nv_bfloat16* __restrict__ wproj,
                           __nv_bfloat16* __restrict__ wfc1, __nv_bfloat16* __restrict__ wfc2) {
    int idx = blockIdx.x * 256 + threadIdx.x;
    if (idx >= S_TOT) return;
    const float* w; __nv_bfloat16* wt; int K, N, l;
    if (idx < S_QKV) {
        w = qkv_w; wt = wqkv; K = CC; N = 3*CC; l = idx;
    } else if (idx < S_QKV + S_PROJ) {
        w = proj_w; wt = wproj; K = CC; N = CC; l = idx - S_QKV;
    } else if (idx < S_QKV + S_PROJ + S_FC1) {
        w = fc1_w; wt = wfc1; K = CC; N = HID; l = idx - S_QKV - S_PROJ;
    } else {
        w = fc2_w; wt = wfc2; K = HID; N = CC; l = idx - S_QKV - S_PROJ - S_FC1;
    }
    const int n = l / K, k = l % K;
    wt[l] = __float2bfloat16(w[(size_t)k * N + n]);
}

// ---------------------------------------------------------------------------
// Block reduction (128 threads)
// ---------------------------------------------------------------------------
__device__ __forceinline__ float block_sum128(float v) {
    __shared__ float sh[4];
    #pragma unroll
    for (int o = 16; o > 0; o >>= 1) v += __shfl_xor_sync(0xffffffffu, v, o);
    if ((threadIdx.x & 31) == 0) sh[threadIdx.x >> 5] = v;
    __syncthreads();
    float r = sh[0] + sh[1] + sh[2] + sh[3];
    __syncthreads();
    return r;
}

// ---------------------------------------------------------------------------
// LayerNorm -> bf16 (optionally shift + window-partition gather)
// ---------------------------------------------------------------------------
template<bool WINDOWED>
__global__ void ln_kernel(const float* __restrict__ x, const float* __restrict__ w,
                          const float* __restrict__ b, __nv_bfloat16* __restrict__ out) {
    const int t = blockIdx.x;
    int src;
    if (WINDOWED) {
        const int win = t / NTOK, n = t % NTOK;
        const int bb = win >> 6, wh = (win >> 3) & 7, ww = win & 7;
        const int i = n / WIN, j = n % WIN;
        int h = wh * WIN + i + SHIFT;  if (h >= HH) h -= HH;
        int wc = ww * WIN + j + SHIFT; if (wc >= WW_DIM) wc -= WW_DIM;
        src = (bb * HH + h) * WW_DIM + wc;
    } else {
        src = t;
    }
    const float* xin = x + (size_t)src * CC;
    const int tid = threadIdx.x;
    const float v0 = xin[tid], v1 = xin[tid + 128], v2 = xin[tid + 256];
    const float mean = block_sum128(v0 + v1 + v2) * (1.0f / CC);
    const float d0 = v0 - mean, d1 = v1 - mean, d2 = v2 - mean;
    const float var = block_sum128(d0*d0 + d1*d1 + d2*d2) * (1.0f / CC);
    const float rstd = rsqrtf(var + 1e-5f);
    __nv_bfloat16* o = out + (size_t)t * CC;
    o[tid]       = __float2bfloat16(d0 * rstd * w[tid]       + b[tid]);
    o[tid + 128] = __float2bfloat16(d1 * rstd * w[tid + 128] + b[tid + 128]);
    o[tid + 256] = __float2bfloat16(d2 * rstd * w[tid + 256] + b[tid + 256]);
}

// ---------------------------------------------------------------------------
// HMMA bf16 GEMM: Out[M,N] = A[M,K] @ Bt[N,K]^T
// BM=BN=128, BK=32, 256 threads (8 warps, 4x2), warp tile 32x64.
// cp.async double-buffered mainloop.
// MODE 0: +bias -> bf16                     (qkv)
// MODE 1: +bias, scatter+resid(x) -> f32    (proj)
// MODE 2: +bias, GELU -> bf16               (fc1)
// MODE 3: +bias, +resid(y) -> f32           (fc2)
// ---------------------------------------------------------------------------
template<int MODE>
__global__ void __launch_bounds__(256, 2)
hmma_gemm(const __nv_bfloat16* __restrict__ A, const __nv_bfloat16* __restrict__ Bt,
          const float* __restrict__ bias, const float* __restrict__ resid,
          void* __restrict__ OutV, int Nn, int K) {
    __shared__ __nv_bfloat16 sA[2][128][40];   // pad: 80B row stride, LDSM conflict-free
    __shared__ __nv_bfloat16 sB[2][128][40];

    const int tid  = threadIdx.x;
    const int lane = tid & 31, warp = tid >> 5;
    const int m0 = (warp & 3) * 32;       // warp M offset in tile
    const int n0 = (warp >> 2) * 64;      // warp N offset in tile
    const int row0 = blockIdx.y * 128;
    const int col0 = blockIdx.x * 128;

    // per-thread load slots (2 x uint4 per array per chunk)
    const int ld_r0 = tid >> 2,           ld_c0 = (tid & 3) * 8;
    const int ld_r1 = (tid + 256) >> 2,   ld_c1 = ld_c0;

    float acc[2][8][4];
    #pragma unroll
    for (int mt = 0; mt < 2; mt++)
        #pragma unroll
        for (int nt = 0; nt < 8; nt++)
            #pragma unroll
            for (int i = 0; i < 4; i++) acc[mt][nt][i] = 0.0f;

    // ldmatrix address components
    const int a_r = lane & 15, a_c8 = (lane >> 4) * 8;
    const int b_g = lane >> 3, b_r = lane & 7;
    const int b_row_off = ((b_g >> 1) << 3) + b_r;   // 0..15
    const int b_c8 = (b_g & 1) * 8;

    const int nch = K >> 5;

    // prologue: chunk 0 -> buffer 0
    {
        CP_ASYNC16(smem_u32(&sA[0][ld_r0][ld_c0]), &A[(size_t)(row0 + ld_r0) * K + ld_c0]);
        CP_ASYNC16(smem_u32(&sB[0][ld_r0][ld_c0]), &Bt[(size_t)(col0 + ld_r0) * K + ld_c0]);
        CP_ASYNC16(smem_u32(&sA[0][ld_r1][ld_c1]), &A[(size_t)(row0 + ld_r1) * K + ld_c1]);
        CP_ASYNC16(smem_u32(&sB[0][ld_r1][ld_c1]), &Bt[(size_t)(col0 + ld_r1) * K + ld_c1]);
        CP_COMMIT();
    }

    for (int kc = 0; kc < nch; kc++) {
        const int buf = kc & 1;
        if (kc + 1 < nch) {
            const int nb = (kc + 1) & 1;
            const int ko = (kc + 1) * 32;
            CP_ASYNC16(smem_u32(&sA[nb][ld_r0][ld_c0]), &A[(size_t)(row0 + ld_r0) * K + ko + ld_c0]);
            CP_ASYNC16(smem_u32(&sB[nb][ld_r0][ld_c0]), &Bt[(size_t)(col0 + ld_r0) * K + ko + ld_c0]);
            CP_ASYNC16(smem_u32(&sA[nb][ld_r1][ld_c1]), &A[(size_t)(row0 + ld_r1) * K + ko + ld_c1]);
            CP_ASYNC16(smem_u32(&sB[nb][ld_r1][ld_c1]), &Bt[(size_t)(col0 + ld_r1) * K + ko + ld_c1]);
            CP_COMMIT();
            CP_WAIT1();
        } else {
            CP_WAIT0();
        }
        __syncthreads();

        #pragma unroll
        for (int kk = 0; kk < 32; kk += 16) {
            uint32_t afr[2][4];
            #pragma unroll
            for (int mt = 0; mt < 2; mt++) {
                const uint32_t addr = smem_u32(&sA[buf][m0 + mt * 16 + a_r][kk + a_c8]);
                LDSM_X4(afr[mt][0], afr[mt][1], afr[mt][2], afr[mt][3], addr);
            }
            uint32_t bfr[8][2];
            #pragma unroll
            for (int nt2 = 0; nt2 < 4; nt2++) {
                const uint32_t addr = smem_u32(&sB[buf][n0 + nt2 * 16 + b_row_off][kk + b_c8]);
                LDSM_X4(bfr[nt2*2][0], bfr[nt2*2][1], bfr[nt2*2+1][0], bfr[nt2*2+1][1], addr);
            }
            #pragma unroll
            for (int mt = 0; mt < 2; mt++)
                #pragma unroll
                for (int nt = 0; nt < 8; nt++)
                    MMA16816(acc[mt][nt], afr[mt], bfr[nt]);
        }
        __syncthreads();
    }

    // epilogue: thread holds (r, c..c+1) and (r+8, c..c+1) per (mt, nt)
    #pragma unroll
    for (int mt = 0; mt < 2; mt++) {
        #pragma unroll
        for (int half = 0; half < 2; half++) {
            const int r = row0 + m0 + mt * 16 + (lane >> 2) + half * 8;
            size_t obase;
            if (MODE == 1) {
                const int win = r / NTOK, n = r % NTOK;
                const int bb = win >> 6, wh = (win >> 3) & 7, ww = win & 7;
                const int ii = n / WIN, jj = n % WIN;
                int h = wh * WIN + ii + SHIFT;  if (h >= HH) h -= HH;
                int wc = ww * WIN + jj + SHIFT; if (wc >= WW_DIM) wc -= WW_DIM;
                obase = ((size_t)(bb * HH + h) * WW_DIM + wc) * CC;
            } else {
                obase = (size_t)r * Nn;
            }
            #pragma unroll
            for (int nt = 0; nt < 8; nt++) {
                const int c = col0 + n0 + nt * 8 + (lane & 3) * 2;
                float v0 = acc[mt][nt][half * 2 + 0] + bias[c];
                float v1 = acc[mt][nt][half * 2 + 1] + bias[c + 1];
                if (MODE == 2) {
                    v0 = 0.5f * v0 * (1.0f + erff(v0 * 0.70710678118654752f));
                    v1 = 0.5f * v1 * (1.0f + erff(v1 * 0.70710678118654752f));
                }
                if (MODE == 0 || MODE == 2) {
                    __nv_bfloat16* Out = (__nv_bfloat16*)OutV;
                    *reinterpret_cast<__nv_bfloat162*>(Out + obase + c) =
                        __floats2bfloat162_rn(v0, v1);
                } else {
                    float* Out = (float*)OutV;
                    const float2 rr2 = *reinterpret_cast<const float2*>(&resid[obase + c]);
                    float2 o2 = make_float2(v0 + rr2.x, v1 + rr2.y);
                    *reinterpret_cast<float2*>(Out + obase + c) = o2;
                }
            }
        }
    }
}

// ---------------------------------------------------------------------------
// Windowed attention: block = (window, head-pair), 128 threads.
// K/V bf16 in smem (broadcast reads), scores f32 in smem (stride 53), q in regs.
// Score dot-product uses 4 independent partial accumulators (chain 16 -> 4).
// ---------------------------------------------------------------------------
__global__ void __launch_bounds__(128)
attn_kernel(const __nv_bfloat16* __restrict__ qkv, const float* __restrict__ rpb,
            __nv_bfloat16* __restrict__ out) {
    __shared__ __nv_bfloat16 ks[2][NTOK][DH];
    __shared__ __nv_bfloat16 vs[2][NTOK][DH];
    __shared__ float S[2][NTOK][53];

    const int win = blockIdx.x;
    const int hp  = blockIdx.y;          // head pair 0..5
    const int tid = threadIdx.x;
    const int hh  = tid >> 6;            // 0/1
    const int n   = tid & 63;
    const int head = hp * 2 + hh;

    // cooperative K/V load: 196 rows of 64B (k then v, both heads)
    const size_t wbase = (size_t)win * NTOK * (3 * CC);
    for (int idx = tid; idx < 196 * 4; idx += 128) {
        const int row = idx >> 2, c = idx & 3;
        const int kv = row / 98;               // 0=k, 1=v
        const int rr = row % 98;
        const int hx = rr / NTOK, nn = rr % NTOK;
        const uint4 u = *reinterpret_cast<const uint4*>(
            qkv + wbase + (size_t)nn * (3 * CC) + (kv + 1) * CC + (hp * 2 + hx) * DH + c * 8);
        __nv_bfloat16* dst = (kv == 0 ? &ks[hx][nn][0] : &vs[hx][nn][0]);
        *reinterpret_cast<uint4*>(dst + c * 8) = u;
    }
    __syncthreads();

    if (n < NTOK) {
        // q row into registers (scaled)
        float q[DH];
        {
            const __nv_bfloat16* qp = qkv + wbase + (size_t)n * (3 * CC) + head * DH;
            #pragma unroll
            for (int c = 0; c < 4; c++) {
                const uint4 u = *reinterpret_cast<const uint4*>(qp + c * 8);
                const uint32_t w4[4] = {u.x, u.y, u.z, u.w};
                #pragma unroll
                for (int j = 0; j < 4; j++) {
                    const float2 fv = __bfloat1622float2(
                        *reinterpret_cast<const __nv_bfloat162*>(&w4[j]));
                    q[c*8 + j*2]     = fv.x * SCALE;
                    q[c*8 + j*2 + 1] = fv.y * SCALE;
                }
            }
        }
        const int wh = (win >> 3) & 7, ww = win & 7;
        const int in_ = n / WIN, jn = n % WIN;
        const int hn = wh * WIN + in_, wn = ww * WIN + jn;
        const int rn = (hn < HH-WIN ? 0 : (hn < HH-SHIFT ? 1 : 2)) * 3
                     + (wn < WW_DIM-WIN ? 0 : (wn < WW_DIM-SHIFT ? 1 : 2));

        // scores (4 independent partial sums break the FMA dependency chain)
        for (int m = 0; m < NTOK; m++) {
            const int im = m / WIN, jm = m % WIN;
            const int hm = wh * WIN + im, wm = ww * WIN + jm;
            const int rm = (hm < HH-WIN ? 0 : (hm < HH-SHIFT ? 1 : 2)) * 3
                         + (wm < WW_DIM-WIN ? 0 : (wm < WW_DIM-SHIFT ? 1 : 2));
            const int rel = (in_ - im + WIN - 1) * (2*WIN - 1) + (jn - jm + WIN - 1);
            const float sb = rpb[rel * HEADS + head] + (rn != rm ? -100.0f : 0.0f);
            const __nv_bfloat162* kp = reinterpret_cast<const __nv_bfloat162*>(&ks[hh][m][0]);
            float p0 = 0.0f, p1 = 0.0f, p2 = 0.0f, p3 = 0.0f;
            #pragma unroll
            for (int d2 = 0; d2 < 4; d2++) {
                const float2 k0 = __bfloat1622float2(kp[d2]);
                const float2 k1 = __bfloat1622float2(kp[d2 + 4]);
                const float2 k2 = __bfloat1622float2(kp[d2 + 8]);
                const float2 k3 = __bfloat1622float2(kp[d2 + 12]);
                p0 += q[2*d2]      * k0.x + q[2*d2 + 1]  * k0.y;
                p1 += q[2*d2 + 8]  * k1.x + q[2*d2 + 9]  * k1.y;
                p2 += q[2*d2 + 16] * k2.x + q[2*d2 + 17] * k2.y;
                p3 += q[2*d2 + 24] * k3.x + q[2*d2 + 25] * k3.y;
            }
            S[hh][n][m] = sb + ((p0 + p1) + (p2 + p3));
        }
        // softmax over own row
        float mx = -1e30f;
        for (int m = 0; m < NTOK; m++) mx = fmaxf(mx, S[hh][n][m]);
        float sum = 0.0f;
        for (int m = 0; m < NTOK; m++) {
            const float e = __expf(S[hh][n][m] - mx);
            S[hh][n][m] = e;
            sum += e;
        }
        const float inv = 1.0f / sum;
        // A @ V
        float acc[DH];
        #pragma unroll
        for (int d = 0; d < DH; d++) acc[d] = 0.0f;
        for (int m = 0; m < NTOK; m++) {
            const float p = S[hh][n][m];
            const __nv_bfloat162* vp = reinterpret_cast<const __nv_bfloat162*>(&vs[hh][m][0]);
            #pragma unroll
            for (int d2 = 0; d2 < 16; d2++) {
                const float2 vv = __bfloat1622float2(vp[d2]);
                acc[2*d2]   += p * vv.x;
                acc[2*d2+1] += p * vv.y;
            }
        }
        // store
        __nv_bfloat16* op = out + (size_t)(win * NTOK + n) * CC + head * DH;
        #pragma unroll
        for (int c = 0; c < 4; c++) {
            uint4 u;
            uint32_t* uw = &u.x;
            #pragma unroll
            for (int j = 0; j < 4; j++) {
                const __nv_bfloat162 hv = __floats2bfloat162_rn(acc[c*8 + j*2] * inv,
                                                                acc[c*8 + j*2 + 1] * inv);
                uw[j] = *reinterpret_cast<const uint32_t*>(&hv);
            }
            *reinterpret_cast<uint4*>(op + c * 8) = u;
        }
    }
}

// ---------------------------------------------------------------------------
// Launch
// ---------------------------------------------------------------------------
extern "C" void kernel_launch(void* const* d_in, const int* in_sizes, int n_in,
                              void* d_out, int out_size) {
    const float* x       = (const float*)d_in[0];
    const float* norm1_w = (const float*)d_in[1];
    const float* norm1_b = (const float*)d_in[2];
    const float* qkv_w   = (const float*)d_in[3];
    const float* qkv_b   = (const float*)d_in[4];
    const float* proj_w  = (const float*)d_in[5];
    const float* proj_b  = (const float*)d_in[6];
    const float* rpb     = (const float*)d_in[7];
    const float* norm2_w = (const float*)d_in[8];
    const float* norm2_b = (const float*)d_in[9];
    const float* fc1_w   = (const float*)d_in[10];
    const float* fc1_b   = (const float*)d_in[11];
    const float* fc2_w   = (const float*)d_in[12];
    const float* fc2_b   = (const float*)d_in[13];
    float* out = (float*)d_out;

    __nv_bfloat16 *xw, *qkv, *att, *m, *h, *wqkv, *wproj, *wfc1, *wfc2;
    float *y;
    cudaGetSymbolAddress((void**)&xw,   g_xw);
    cudaGetSymbolAddress((void**)&qkv,  g_qkv);
    cudaGetSymbolAddress((void**)&att,  g_att);
    cudaGetSymbolAddress((void**)&y,    g_y);
    cudaGetSymbolAddress((void**)&m,    g_m);
    cudaGetSymbolAddress((void**)&h,    g_h);
    cudaGetSymbolAddress((void**)&wqkv, g_wqkv);
    cudaGetSymbolAddress((void**)&wproj,g_wproj);
    cudaGetSymbolAddress((void**)&wfc1, g_wfc1);
    cudaGetSymbolAddress((void**)&wfc2, g_wfc2);

    // weight transposes (bf16, [N,K]) — single merged launch
    wtrans_all<<<(S_TOT + 255)/256, 256>>>(qkv_w, proj_w, fc1_w, fc2_w,
                                           wqkv, wproj, wfc1, wfc2);

    // 1. LN1 + shift + window partition -> bf16
    ln_kernel<true><<<TOK, 128>>>(x, norm1_w, norm1_b, xw);
    // 2. qkv GEMM
    hmma_gemm<0><<<dim3((3*CC)/128, TOK/128), 256>>>(xw, wqkv, qkv_b, nullptr, qkv, 3*CC, CC);
    // 3. attention
    attn_kernel<<<dim3(BATCH*NWIN, HEADS/2), 128>>>(qkv, rpb, att);
    // 4. proj GEMM + window-reverse + unshift + residual -> y (f32)
    hmma_gemm<1><<<dim3(CC/128, TOK/128), 256>>>(att, wproj, proj_b, x, y, CC, CC);
    // 5. LN2 -> bf16
    ln_kernel<false><<<TOK, 128>>>(y, norm2_w, norm2_b, m);
    // 6. fc1 + GELU -> bf16
    hmma_gemm<2><<<dim3(HID/128, TOK/128), 256>>>(m, wfc1, fc1_b, nullptr, h, HID, CC);
    // 7. fc2 + residual -> d_out (f32)
    hmma_gemm<3><<<dim3(CC/128, TOK/128), 256>>>(h, wfc2, fc2_b, y, out, CC, HID);
}